// round 7
// baseline (speedup 1.0000x reference)
#include <cuda_runtime.h>

#define NBATCH 4
#define CCH 256
#define FH 100
#define FW 152
#define HW (FH*FW)           // 15200
#define FWC (FW*CCH)         // 38912
#define NROI 4000
#define HALF_CH 128
#define HALF_OUT (HALF_CH*49)      // 6272 floats, linear 16B-aligned region
#define SMEM_BYTES (HALF_OUT*4)    // 25088 B

// NHWC scratch (device global: allocation-free scratch per harness rules)
__device__ float g_nhwc[NBATCH * HW * CCH];

// ---------------------------------------------------------------------------
// Kernel A: NCHW -> NHWC transpose. 128ch x 32hw tiles (4x the old 32x32):
// 3800 blocks instead of 15200, 16 independent LDGs per thread for deep MLP.
// tile stride 33 -> both LDS patterns conflict-free. __ldcs on the source:
// features are read exactly once, don't let them pollute L2.
// ---------------------------------------------------------------------------
__global__ __launch_bounds__(256) void transpose_kernel(const float* __restrict__ in) {
    __shared__ float tile[128][33];
    const int b   = blockIdx.z;
    const int hw0 = blockIdx.x * 32;
    const int c0  = blockIdx.y * 128;
    const int x   = threadIdx.x;
    const int y   = threadIdx.y;

    const float* src = in + (size_t)b * CCH * HW + (size_t)(c0 + y) * HW + hw0 + x;
    #pragma unroll
    for (int k = 0; k < 16; k++)                    // c rows y, y+8, ..., y+120
        tile[y + 8*k][x] = __ldcs(src + (size_t)(8*k) * HW);
    __syncthreads();

    // write NHWC: for each hw row, 128 consecutive channels
    float* dst = g_nhwc + (size_t)b * HW * CCH + (size_t)hw0 * CCH + c0 + x;
    #pragma unroll
    for (int k = 0; k < 4; k++) {                   // hw = y, y+8, y+16, y+24
        const int hw = y + 8*k;
        #pragma unroll
        for (int m = 0; m < 4; m++)                 // channel quarters
            dst[(size_t)hw * CCH + 32*m] = tile[x + 32*m][hw];
    }
}

// ---------------------------------------------------------------------------
// Row-group body (round-3 verbatim: the best measured gather loop).
// ---------------------------------------------------------------------------
template<int NR>
__device__ __forceinline__ void process_rows(
    int i0, const float* __restrict__ fbase, int c,
    const int* s_ws, const int* s_hs,
    const float* s_wf, const float* s_hf,
    const float* s_wm, const float* s_hm,
    float* s_out)
{
    float prev[8], cur[8];
    #pragma unroll
    for (int k = 0; k < NR; ++k) {
        const int i = i0 + k;
        const float* r0 = fbase + s_hs[i] * FWC;
        const float hf = s_hf[i];
        const float hm = s_hm[i];

        #pragma unroll
        for (int j = 0; j < 8; j++) {
            const int w0 = s_ws[j];
            float a00 = r0[w0];
            float a01 = r0[w0 + CCH];
            float a10 = r0[w0 + FWC];
            float a11 = r0[w0 + FWC + CCH];
            float wf  = s_wf[j];
            float top = a00 + (a01 - a00) * wf;
            float bot = a10 + (a11 - a10) * wf;
            cur[j] = (top + (bot - top) * hf) * (hm * s_wm[j]);
        }

        if (k > 0) {
            int rb = c * 49 + (i - 1) * 7;
            #pragma unroll
            for (int j = 0; j < 7; j++)
                s_out[rb + j] = 0.25f * (prev[j] + prev[j+1] + cur[j] + cur[j+1]);
        }
        #pragma unroll
        for (int j = 0; j < 8; j++) prev[j] = cur[j];
    }
}

// ---------------------------------------------------------------------------
// Kernel B (round-3 structure, 102us measured): one 256-thread block per
// (roi, channel-half), 128 channels x 2 row-groups, scalar gathers,
// 25KB linear smem stage, no reg cap (ptxas -> 64 regs, 4 CTAs, 32 warps).
// Flush uses __stcs: 200MB output stream must not evict the NHWC working
// set from L2.
// ---------------------------------------------------------------------------
__global__ __launch_bounds__(256) void roi_kernel(
    const float* __restrict__ rois,
    const int*   __restrict__ bids,
    float*       __restrict__ out)
{
    extern __shared__ float s_out[];   // [128][49]
    __shared__ int   s_ws[8], s_hs[8];
    __shared__ float s_wf[8], s_hf[8], s_wm[8], s_hm[8];

    const int bx   = blockIdx.x;
    const int r    = bx >> 1;
    const int half = bx & 1;
    const int t    = threadIdx.x;
    const int c    = t & (HALF_CH - 1);
    const int g    = t >> 7;           // warps 0-3: g=0, warps 4-7: g=1

    if (t < 8) {
        float x1 = rois[r*4 + 0] * 0.0625f;
        float x2 = rois[r*4 + 2] * 0.0625f;
        float bw = fmaxf(x2 - x1 + 1.0f, 0.0f) * (1.0f / 7.0f);
        float w  = x1 + (float)t * bw;
        s_wm[t]  = (w >= 0.0f && w < (float)FW) ? 1.0f : 0.0f;
        float wsf = fminf(fmaxf(floorf(w), 0.0f), (float)(FW - 2));
        s_ws[t]  = (int)wsf * CCH;     // pre-scaled column offset (floats)
        s_wf[t]  = w - wsf;
    } else if (t < 16) {
        int i = t & 7;
        float y1 = rois[r*4 + 1] * 0.0625f;
        float y2 = rois[r*4 + 3] * 0.0625f;
        float bh = fmaxf(y2 - y1 + 1.0f, 0.0f) * (1.0f / 7.0f);
        float h  = y1 + (float)i * bh;
        s_hm[i]  = (h >= 0.0f && h < (float)FH) ? 1.0f : 0.0f;
        float hsf = fminf(fmaxf(floorf(h), 0.0f), (float)(FH - 2));
        s_hs[i]  = (int)hsf;
        s_hf[i]  = h - hsf;
    }
    __syncthreads();

    const int b = bids[r];
    const float* fbase = g_nhwc + (size_t)b * HW * CCH + half * HALF_CH + c;

    if (g == 0)
        process_rows<5>(0, fbase, c, s_ws, s_hs, s_wf, s_hf, s_wm, s_hm, s_out);
    else
        process_rows<4>(4, fbase, c, s_ws, s_hs, s_wf, s_hf, s_wm, s_hm, s_out);

    __syncthreads();

    // Coalesced streaming flush: this half's output region is linear.
    float4*       op = (float4*)(out + (size_t)r * (CCH*49) + half * HALF_OUT);
    const float4* sp = (const float4*)s_out;
    #pragma unroll
    for (int m = t; m < HALF_OUT / 4; m += 256)
        __stcs(op + m, sp[m]);
}

// ---------------------------------------------------------------------------
extern "C" void kernel_launch(void* const* d_in, const int* in_sizes, int n_in,
                              void* d_out, int out_size) {
    const float* features = (const float*)d_in[0];
    const float* rois     = (const float*)d_in[1];
    const int*   bids     = (const int*)d_in[2];
    float*       out      = (float*)d_out;

    dim3 tgrid(HW / 32, CCH / 128, NBATCH);   // (475, 2, 4) = 3800 blocks
    transpose_kernel<<<tgrid, dim3(32, 8)>>>(features);

    cudaFuncSetAttribute(roi_kernel,
                         cudaFuncAttributeMaxDynamicSharedMemorySize,
                         SMEM_BYTES);
    roi_kernel<<<NROI * 2, 256, SMEM_BYTES>>>(rois, bids, out);
}

// round 8
// speedup vs baseline: 1.3256x; 1.3256x over previous
#include <cuda_runtime.h>

#define NBATCH 4
#define CCH 256
#define FH 100
#define FW 152
#define HW (FH*FW)           // 15200
#define FWC (FW*CCH)         // 38912
#define NROI 4000
#define HALF_CH 128
#define HALF_OUT (HALF_CH*49)      // 6272 floats, linear 16B-aligned region
#define SMEM_BYTES (HALF_OUT*4)    // 25088 B

// NHWC scratch (device global: allocation-free scratch per harness rules)
__device__ float g_nhwc[NBATCH * HW * CCH];

// ---------------------------------------------------------------------------
// Kernel A: NCHW -> NHWC transpose. 128ch x 32hw tiles: 3800 blocks,
// 16 independent LDGs per thread (deep MLP). Measured ~15us in round 7.
// __ldcs on source: features are read exactly once.
// ---------------------------------------------------------------------------
__global__ __launch_bounds__(256) void transpose_kernel(const float* __restrict__ in) {
    __shared__ float tile[128][33];
    const int b   = blockIdx.z;
    const int hw0 = blockIdx.x * 32;
    const int c0  = blockIdx.y * 128;
    const int x   = threadIdx.x;
    const int y   = threadIdx.y;

    const float* src = in + (size_t)b * CCH * HW + (size_t)(c0 + y) * HW + hw0 + x;
    #pragma unroll
    for (int k = 0; k < 16; k++)                    // c rows y, y+8, ..., y+120
        tile[y + 8*k][x] = __ldcs(src + (size_t)(8*k) * HW);
    __syncthreads();

    float* dst = g_nhwc + (size_t)b * HW * CCH + (size_t)hw0 * CCH + c0 + x;
    #pragma unroll
    for (int k = 0; k < 4; k++) {                   // hw = y, y+8, y+16, y+24
        const int hw = y + 8*k;
        #pragma unroll
        for (int m = 0; m < 4; m++)                 // channel quarters
            dst[(size_t)hw * CCH + 32*m] = tile[x + 32*m][hw];
    }
}

// ---------------------------------------------------------------------------
// Row-group body (round-3 verbatim: best measured gather loop, 102us).
// ---------------------------------------------------------------------------
template<int NR>
__device__ __forceinline__ void process_rows(
    int i0, const float* __restrict__ fbase, int c,
    const int* s_ws, const int* s_hs,
    const float* s_wf, const float* s_hf,
    const float* s_wm, const float* s_hm,
    float* s_out)
{
    float prev[8], cur[8];
    #pragma unroll
    for (int k = 0; k < NR; ++k) {
        const int i = i0 + k;
        const float* r0 = fbase + s_hs[i] * FWC;
        const float hf = s_hf[i];
        const float hm = s_hm[i];

        #pragma unroll
        for (int j = 0; j < 8; j++) {
            const int w0 = s_ws[j];
            float a00 = r0[w0];
            float a01 = r0[w0 + CCH];
            float a10 = r0[w0 + FWC];
            float a11 = r0[w0 + FWC + CCH];
            float wf  = s_wf[j];
            float top = a00 + (a01 - a00) * wf;
            float bot = a10 + (a11 - a10) * wf;
            cur[j] = (top + (bot - top) * hf) * (hm * s_wm[j]);
        }

        if (k > 0) {
            int rb = c * 49 + (i - 1) * 7;
            #pragma unroll
            for (int j = 0; j < 7; j++)
                s_out[rb + j] = 0.25f * (prev[j] + prev[j+1] + cur[j] + cur[j+1]);
        }
        #pragma unroll
        for (int j = 0; j < 8; j++) prev[j] = cur[j];
    }
}

// ---------------------------------------------------------------------------
// Kernel B (round-3 verbatim, 102us measured): one 256-thread block per
// (roi, channel-half), 128 channels x 2 row-groups, scalar gathers, 25KB
// linear smem stage, PLAIN float4 flush (round 7 proved __stcs costs ~40us),
// no reg cap (ptxas -> 64 regs, 4 CTAs/SM, 32 warps — the empirical optimum
// of the regs-vs-warps tiers tried in rounds 1-6).
// ---------------------------------------------------------------------------
__global__ __launch_bounds__(256) void roi_kernel(
    const float* __restrict__ rois,
    const int*   __restrict__ bids,
    float*       __restrict__ out)
{
    extern __shared__ float s_out[];   // [128][49]
    __shared__ int   s_ws[8], s_hs[8];
    __shared__ float s_wf[8], s_hf[8], s_wm[8], s_hm[8];

    const int bx   = blockIdx.x;
    const int r    = bx >> 1;
    const int half = bx & 1;
    const int t    = threadIdx.x;
    const int c    = t & (HALF_CH - 1);
    const int g    = t >> 7;           // warps 0-3: g=0, warps 4-7: g=1

    if (t < 8) {
        float x1 = rois[r*4 + 0] * 0.0625f;
        float x2 = rois[r*4 + 2] * 0.0625f;
        float bw = fmaxf(x2 - x1 + 1.0f, 0.0f) * (1.0f / 7.0f);
        float w  = x1 + (float)t * bw;
        s_wm[t]  = (w >= 0.0f && w < (float)FW) ? 1.0f : 0.0f;
        float wsf = fminf(fmaxf(floorf(w), 0.0f), (float)(FW - 2));
        s_ws[t]  = (int)wsf * CCH;     // pre-scaled column offset (floats)
        s_wf[t]  = w - wsf;
    } else if (t < 16) {
        int i = t & 7;
        float y1 = rois[r*4 + 1] * 0.0625f;
        float y2 = rois[r*4 + 3] * 0.0625f;
        float bh = fmaxf(y2 - y1 + 1.0f, 0.0f) * (1.0f / 7.0f);
        float h  = y1 + (float)i * bh;
        s_hm[i]  = (h >= 0.0f && h < (float)FH) ? 1.0f : 0.0f;
        float hsf = fminf(fmaxf(floorf(h), 0.0f), (float)(FH - 2));
        s_hs[i]  = (int)hsf;
        s_hf[i]  = h - hsf;
    }
    __syncthreads();

    const int b = bids[r];
    const float* fbase = g_nhwc + (size_t)b * HW * CCH + half * HALF_CH + c;

    if (g == 0)
        process_rows<5>(0, fbase, c, s_ws, s_hs, s_wf, s_hf, s_wm, s_hm, s_out);
    else
        process_rows<4>(4, fbase, c, s_ws, s_hs, s_wf, s_hf, s_wm, s_hm, s_out);

    __syncthreads();

    // Coalesced flush: this half's output region is linear in global memory.
    float4*       op = (float4*)(out + (size_t)r * (CCH*49) + half * HALF_OUT);
    const float4* sp = (const float4*)s_out;
    #pragma unroll
    for (int m = t; m < HALF_OUT / 4; m += 256)
        op[m] = sp[m];
}

// ---------------------------------------------------------------------------
extern "C" void kernel_launch(void* const* d_in, const int* in_sizes, int n_in,
                              void* d_out, int out_size) {
    const float* features = (const float*)d_in[0];
    const float* rois     = (const float*)d_in[1];
    const int*   bids     = (const int*)d_in[2];
    float*       out      = (float*)d_out;

    dim3 tgrid(HW / 32, CCH / 128, NBATCH);   // (475, 2, 4) = 3800 blocks
    transpose_kernel<<<tgrid, dim3(32, 8)>>>(features);

    cudaFuncSetAttribute(roi_kernel,
                         cudaFuncAttributeMaxDynamicSharedMemorySize,
                         SMEM_BYTES);
    roi_kernel<<<NROI * 2, 256, SMEM_BYTES>>>(rois, bids, out);
}